// round 1
// baseline (speedup 1.0000x reference)
#include <cuda_runtime.h>

// RuleGraphConvLayer — GB300 sm_103a
//
// Restructured algebra:
//   contrib_e = s_e*(feat[dst]@Wn81) + s_e*(feat[src][3:]@Wn[3:81]) + bond_e@Wb
//   agg[n]    = G[n]@Wn81 + c_n*(feat[n][3:]@Wn[3:81]) + bond_agg[n]@Wb
// where G[n] = sum s_e*feat[dst_e], c_n = sum s_e, bond_agg[n] = sum bond_e
// (all grouped by src). Final:
//   out[n] = [feat(81) | H(81) | bond_agg(22)] @ [w_s ; w_n]   (K=184, N=64)
//   H[k] = G[k] + (k>=3 ? c_n*feat[k] : 0)

#define MAX_NODES 100000
#define NF 81      // node features
#define NB 22      // bond features
#define OC 64      // output channels
#define KTOT 184   // 81 + 81 + 22
#define WPITCH 188 // W smem row pitch (floats). 188%32==28 -> conflict-free LDS.128 tiling
#define NPB 32     // nodes per block in final kernel

__device__ __align__(16) float g_G[MAX_NODES * NF];
__device__ __align__(16) float g_bond[MAX_NODES * NB];
__device__ __align__(16) float g_coeff[MAX_NODES];

// ---------------------------------------------------------------------------
// K0: zero the accumulators (float4, all counts divisible by 4)
// ---------------------------------------------------------------------------
__global__ void zero_kernel(int n_nodes) {
    int i = blockIdx.x * blockDim.x + threadIdx.x;
    int ng = (n_nodes * NF) >> 2;
    int nb = (n_nodes * NB) >> 2;
    int nc = n_nodes >> 2;
    float4 z = make_float4(0.f, 0.f, 0.f, 0.f);
    if (i < ng) {
        reinterpret_cast<float4*>(g_G)[i] = z;
    } else if (i < ng + nb) {
        reinterpret_cast<float4*>(g_bond)[i - ng] = z;
    } else if (i < ng + nb + nc) {
        reinterpret_cast<float4*>(g_coeff)[i - ng - nb] = z;
    }
}

// ---------------------------------------------------------------------------
// K1: edge pass. One warp per edge.
//   G[src]        += s * feat[dst]       (81 floats)
//   bond_agg[src] += bond[e]             (22 floats)
//   coeff[src]    += s                   (scalar)
// ---------------------------------------------------------------------------
__global__ void edge_kernel(const float* __restrict__ feat,
                            const float* __restrict__ bond,
                            const int* __restrict__ src,
                            const int* __restrict__ dst,
                            int n_edges) {
    int e = (int)((blockIdx.x * blockDim.x + threadIdx.x) >> 5);
    int lane = threadIdx.x & 31;
    if (e >= n_edges) return;

    int s = __ldg(src + e);
    int d = __ldg(dst + e);
    const float* fs = feat + (size_t)s * NF;
    const float* fd = feat + (size_t)d * NF;

    // broadcast loads (same address across the warp -> 1 request each)
    float dx = __ldg(fs + 0) - __ldg(fd + 0);
    float dy = __ldg(fs + 1) - __ldg(fd + 1);
    float dz = __ldg(fs + 2) - __ldg(fd + 2);
    float dd = dx * dx + dy * dy + dz * dz;
    // reference: d = dist>0 ? dist : 0.01; divide by d*d
    float sc = (dd > 0.f) ? (1.f / dd) : 10000.f;

    float* Gs = g_G + (size_t)s * NF;
    #pragma unroll
    for (int k = lane; k < NF; k += 32) {
        atomicAdd(Gs + k, sc * __ldg(fd + k));
    }
    if (lane < NB) {
        atomicAdd(g_bond + (size_t)s * NB + lane,
                  __ldg(bond + (size_t)e * NB + lane));
    }
    if (lane == 0) {
        atomicAdd(g_coeff + s, sc);
    }
}

// ---------------------------------------------------------------------------
// K2: fused node GEMM.  out[n] = x[n](184) @ Wcat(184x64)
//   x = [feat | G + c*feat*(k>=3) | bond_agg]
// Block: 256 threads = 32 nodes x 8 channel-groups (8 channels per thread,
// strided by 8 so LDS.128 of transposed W rows is bank-conflict-free).
// ---------------------------------------------------------------------------
extern __shared__ float k2_smem[];

__global__ __launch_bounds__(256) void final_kernel(
    const float* __restrict__ feat,
    const float* __restrict__ w_s,   // [81][64]
    const float* __restrict__ w_n,   // [103][64]
    float* __restrict__ out,         // [n_nodes][64]
    int n_nodes) {

    float* Wsh = k2_smem;                    // [OC][WPITCH] transposed weights
    float* xsh = Wsh + OC * WPITCH;          // [NPB][KTOT]
    float* csh = xsh + NPB * KTOT;           // [NPB]

    int tid = threadIdx.x;
    int nb0 = blockIdx.x * NPB;

    // Load combined weight matrix, transposed: Wsh[c][k]
    //   rows 0..80   -> w_s
    //   rows 81..183 -> w_n (rows 0..102)
    for (int idx = tid; idx < KTOT * OC; idx += 256) {
        int k = idx >> 6;      // / OC
        int c = idx & (OC - 1);
        float v = (k < NF) ? __ldg(w_s + k * OC + c)
                           : __ldg(w_n + (k - NF) * OC + c);
        Wsh[c * WPITCH + k] = v;
    }
    if (tid < NPB) {
        int node = nb0 + tid;
        csh[tid] = (node < n_nodes) ? g_coeff[node] : 0.f;
    }
    __syncthreads();

    // Fill x rows
    for (int idx = tid; idx < NPB * NF; idx += 256) {
        int n = idx / NF;
        int k = idx - n * NF;
        int node = nb0 + n;
        if (node < n_nodes) {
            float f = feat[(size_t)node * NF + k];
            xsh[n * KTOT + k] = f;
            float h = g_G[(size_t)node * NF + k];
            if (k >= 3) h += csh[n] * f;
            xsh[n * KTOT + NF + k] = h;
        }
    }
    for (int idx = tid; idx < NPB * NB; idx += 256) {
        int n = idx / NB;
        int j = idx - n * NB;
        int node = nb0 + n;
        if (node < n_nodes) {
            xsh[n * KTOT + 2 * NF + j] = g_bond[(size_t)node * NB + j];
        }
    }
    __syncthreads();

    int node_local = tid >> 3;     // 0..31
    int cgrp = tid & 7;            // channel group; channels cgrp + 8*j
    const float* xrow = xsh + node_local * KTOT;

    float acc[8];
    #pragma unroll
    for (int j = 0; j < 8; j++) acc[j] = 0.f;

    #pragma unroll 2
    for (int k = 0; k < KTOT; k += 4) {
        float4 xv = *reinterpret_cast<const float4*>(xrow + k);
        #pragma unroll
        for (int j = 0; j < 8; j++) {
            float4 wv = *reinterpret_cast<const float4*>(
                Wsh + (cgrp + 8 * j) * WPITCH + k);
            acc[j] += xv.x * wv.x;
            acc[j] += xv.y * wv.y;
            acc[j] += xv.z * wv.z;
            acc[j] += xv.w * wv.w;
        }
    }

    int node = nb0 + node_local;
    if (node < n_nodes) {
        #pragma unroll
        for (int j = 0; j < 8; j++) {
            out[(size_t)node * OC + cgrp + 8 * j] = acc[j];
        }
    }
}

// ---------------------------------------------------------------------------
// Launch
// ---------------------------------------------------------------------------
extern "C" void kernel_launch(void* const* d_in, const int* in_sizes, int n_in,
                              void* d_out, int out_size) {
    const float* feat = (const float*)d_in[0];   // [n_nodes][81]
    const float* bond = (const float*)d_in[1];   // [n_edges][22]
    const float* w_s  = (const float*)d_in[2];   // [81][64]
    const float* w_n  = (const float*)d_in[3];   // [103][64]
    const int*   src  = (const int*)d_in[4];     // [n_edges]
    const int*   dst  = (const int*)d_in[5];     // [n_edges]
    float* out = (float*)d_out;

    int n_nodes = in_sizes[0] / NF;
    int n_edges = in_sizes[4];

    const int k2_bytes = (OC * WPITCH + NPB * KTOT + NPB) * (int)sizeof(float); // 71808
    cudaFuncSetAttribute(final_kernel,
                         cudaFuncAttributeMaxDynamicSharedMemorySize, k2_bytes);

    int total4 = (n_nodes * NF + n_nodes * NB + n_nodes) >> 2;
    zero_kernel<<<(total4 + 255) / 256, 256>>>(n_nodes);

    // one warp per edge, 8 warps per block
    edge_kernel<<<(n_edges + 7) / 8, 256>>>(feat, bond, src, dst, n_edges);

    final_kernel<<<(n_nodes + NPB - 1) / NPB, 256, k2_bytes>>>(
        feat, w_s, w_n, out, n_nodes);
}

// round 2
// speedup vs baseline: 1.2993x; 1.2993x over previous
#include <cuda_runtime.h>

// RuleGraphConvLayer — GB300 sm_103a, round 2
//
// Algebra (grouped by src):
//   G[n]    = sum_e s_e * feat[dst_e]      (81 wide)
//   c[n]    = sum_e s_e                    (packed at G row index 81)
//   bagg[n] = sum_e bond_e                 (22 wide)
//   out[n]  = [feat | G + c*feat*(k>=3) | bagg] @ [w_s ; w_n]   (K=184, N=64)
//
// R2 changes vs R1:
//   * edge pass uses red.global.add.v4.f32 (27 vec REDs/edge vs 104 scalar)
//   * final GEMM: 1 node/thread, 64 acc packed as 32 f32x2, W broadcast from
//     smem, fma.rn.f32x2 (2x fp32 rate), x streamed from global via L1.

#define MAX_NODES 100000
#define NF 81
#define NB 22
#define OC 64
#define GP 84      // G row pitch: 81 G + coeff@81 + 2 pad (336B, 16B aligned)
#define BP 24      // bond row pitch (96B, 16B aligned)

__device__ __align__(16) float g_G[MAX_NODES * GP];
__device__ __align__(16) float g_bond[MAX_NODES * BP];

// ---------------------------------------------------------------------------
// K0: zero accumulators (float4)
// ---------------------------------------------------------------------------
__global__ void zero_kernel(int n_nodes) {
    int i = blockIdx.x * blockDim.x + threadIdx.x;
    int ng = (n_nodes * GP) >> 2;
    int nb = (n_nodes * BP) >> 2;
    float4 z = make_float4(0.f, 0.f, 0.f, 0.f);
    if (i < ng) {
        reinterpret_cast<float4*>(g_G)[i] = z;
    } else if (i < ng + nb) {
        reinterpret_cast<float4*>(g_bond)[i - ng] = z;
    }
}

// ---------------------------------------------------------------------------
// vec4 global reduction-add (no return) — sm_90+ PTX
// ---------------------------------------------------------------------------
__device__ __forceinline__ void red_add_v4(float* p, float a, float b, float c, float d) {
    asm volatile("red.global.add.v4.f32 [%0], {%1, %2, %3, %4};"
                 :: "l"(p), "f"(a), "f"(b), "f"(c), "f"(d) : "memory");
}

// ---------------------------------------------------------------------------
// K1: edge pass. One warp per edge, 27 vec4 REDs.
//   lanes 0..19 : G[src][4l..4l+3]    += s * feat[dst][4l..4l+3]
//   lane  20    : G[src][80..83]      += (s*feat[dst][80], s, 0, 0)
//   lanes 21..26: bond_agg[src][4j..] += bond[e][4j..]   (j = lane-21)
// ---------------------------------------------------------------------------
__global__ __launch_bounds__(256) void edge_kernel(
    const float* __restrict__ feat,
    const float* __restrict__ bond,
    const int* __restrict__ src,
    const int* __restrict__ dst,
    int n_edges) {

    int e = (int)((blockIdx.x * blockDim.x + threadIdx.x) >> 5);
    int lane = threadIdx.x & 31;
    if (e >= n_edges) return;

    int si = __ldg(src + e);
    int di = __ldg(dst + e);
    const float* fs = feat + (size_t)si * NF;
    const float* fd = feat + (size_t)di * NF;

    // warp-uniform broadcast loads
    float dx = __ldg(fs + 0) - __ldg(fd + 0);
    float dy = __ldg(fs + 1) - __ldg(fd + 1);
    float dz = __ldg(fs + 2) - __ldg(fd + 2);
    float dd = dx * dx + dy * dy + dz * dz;
    float sc = (dd > 0.f) ? (1.f / dd) : 10000.f;

    float* Grow = g_G + (size_t)si * GP;

    if (lane < 20) {
        int k = lane << 2;
        red_add_v4(Grow + k,
                   sc * __ldg(fd + k + 0), sc * __ldg(fd + k + 1),
                   sc * __ldg(fd + k + 2), sc * __ldg(fd + k + 3));
    } else if (lane == 20) {
        red_add_v4(Grow + 80, sc * __ldg(fd + 80), sc, 0.f, 0.f);
    } else if (lane < 27) {
        int j = lane - 21;
        const float* be = bond + (size_t)e * NB + (j << 2);
        float b2 = (j < 5) ? __ldg(be + 2) : 0.f;
        float b3 = (j < 5) ? __ldg(be + 3) : 0.f;
        red_add_v4(g_bond + (size_t)si * BP + (j << 2),
                   __ldg(be + 0), __ldg(be + 1), b2, b3);
    }
}

// ---------------------------------------------------------------------------
// K2: final GEMM. One node per thread. 64 channels as 32 packed f32x2 accs.
// W[k][c] staged in smem (184x64 = 47KB), read as warp-broadcast LDS.128.
// x streamed straight from global (each thread walks its own rows -> L1 hits).
// ---------------------------------------------------------------------------
__shared__ float Wsh[184 * OC];

__device__ __forceinline__ void fma2_step(unsigned long long* acc,
                                          const float* wrow, float xv) {
    unsigned long long xx;
    asm("mov.b64 %0, {%1, %1};" : "=l"(xx) : "f"(xv));
    const ulonglong2* w2 = reinterpret_cast<const ulonglong2*>(wrow);
    #pragma unroll
    for (int j = 0; j < 16; j++) {
        ulonglong2 wv = w2[j];
        asm("fma.rn.f32x2 %0, %1, %2, %0;" : "+l"(acc[2 * j + 0]) : "l"(xx), "l"(wv.x));
        asm("fma.rn.f32x2 %0, %1, %2, %0;" : "+l"(acc[2 * j + 1]) : "l"(xx), "l"(wv.y));
    }
}

__global__ __launch_bounds__(256) void final_kernel(
    const float* __restrict__ feat,
    const float* __restrict__ w_s,   // [81][64]
    const float* __restrict__ w_n,   // [103][64]
    float* __restrict__ out,         // [n_nodes][64]
    int n_nodes) {

    int tid = threadIdx.x;
    int node = blockIdx.x * 256 + tid;

    // Stage W: rows 0..80 = w_s, 81..161 = w_n[0..80], 162..183 = w_n[81..102]
    #pragma unroll
    for (int r = 0; r < 46; r++) {
        int idx = r * 256 + tid;           // 46*256 = 11776 = 184*64 exactly
        int k = idx >> 6;
        int c = idx & (OC - 1);
        float v = (k < NF) ? __ldg(w_s + k * OC + c)
                           : __ldg(w_n + (k - NF) * OC + c);
        Wsh[idx] = v;
    }
    __syncthreads();

    if (node >= n_nodes) return;

    const float* frow = feat + (size_t)node * NF;
    const float* Grow = g_G + (size_t)node * GP;
    const float* brow = g_bond + (size_t)node * BP;
    float cn = __ldg(Grow + NF);   // coeff packed at G[81]

    unsigned long long acc[32];
    #pragma unroll
    for (int j = 0; j < 32; j++) acc[j] = 0ull;

    // segment 1: feat (k = 0..80)
    #pragma unroll 3
    for (int k = 0; k < NF; k++) {
        fma2_step(acc, Wsh + k * OC, __ldg(frow + k));
    }
    // segment 2: G + c*feat (k >= 3), rows 81..161 of W
    fma2_step(acc, Wsh + (NF + 0) * OC, __ldg(Grow + 0));
    fma2_step(acc, Wsh + (NF + 1) * OC, __ldg(Grow + 1));
    fma2_step(acc, Wsh + (NF + 2) * OC, __ldg(Grow + 2));
    #pragma unroll 3
    for (int k = 3; k < NF; k++) {
        float xv = __ldg(Grow + k) + cn * __ldg(frow + k);
        fma2_step(acc, Wsh + (NF + k) * OC, xv);
    }
    // segment 3: bond_agg, rows 162..183 of W
    #pragma unroll 2
    for (int k = 0; k < NB; k++) {
        fma2_step(acc, Wsh + (2 * NF + k) * OC, __ldg(brow + k));
    }

    // epilogue: unpack 32 f32x2 -> 64 floats, store as float4
    float* orow = out + (size_t)node * OC;
    #pragma unroll
    for (int j = 0; j < 16; j++) {
        float a0, a1, a2, a3;
        asm("mov.b64 {%0, %1}, %2;" : "=f"(a0), "=f"(a1) : "l"(acc[2 * j + 0]));
        asm("mov.b64 {%0, %1}, %2;" : "=f"(a2), "=f"(a3) : "l"(acc[2 * j + 1]));
        reinterpret_cast<float4*>(orow)[j] = make_float4(a0, a1, a2, a3);
    }
}

// ---------------------------------------------------------------------------
// Launch
// ---------------------------------------------------------------------------
extern "C" void kernel_launch(void* const* d_in, const int* in_sizes, int n_in,
                              void* d_out, int out_size) {
    const float* feat = (const float*)d_in[0];
    const float* bond = (const float*)d_in[1];
    const float* w_s  = (const float*)d_in[2];
    const float* w_n  = (const float*)d_in[3];
    const int*   src  = (const int*)d_in[4];
    const int*   dst  = (const int*)d_in[5];
    float* out = (float*)d_out;

    int n_nodes = in_sizes[0] / NF;
    int n_edges = in_sizes[4];

    int nz4 = (n_nodes * (GP + BP)) >> 2;
    zero_kernel<<<(nz4 + 255) / 256, 256>>>(n_nodes);

    edge_kernel<<<(n_edges + 7) / 8, 256>>>(feat, bond, src, dst, n_edges);

    final_kernel<<<(n_nodes + 255) / 256, 256>>>(feat, w_s, w_n, out, n_nodes);
}

// round 3
// speedup vs baseline: 1.3522x; 1.0408x over previous
#include <cuda_runtime.h>

// RuleGraphConvLayer — GB300 sm_103a, round 3
//
//   G[n]    = sum_e s_e * feat[dst_e]   (81)      [grouped by src]
//   c[n]    = sum_e s_e                 (@G[81])
//   bagg[n] = sum_e bond_e              (22)
//   out[n]  = [feat | G + c*feat*(k>=3) | bagg] @ [w_s ; w_n]   (K=184, N=64)
//
// R3: atomics eliminated. Counting sort groups edges by src, then a
// warp-per-node pass gathers feat[dst]/bond and reduces in registers.

#define MAX_NODES 100000
#define MAX_EDGES 800000
#define NF 81
#define NB 22
#define OC 64
#define GP 84      // G row pitch (81 + coeff@81 + pad)
#define BP 24      // bond row pitch

#define SCAN_T 1024
#define SCAN_E 4
#define SCAN_B (SCAN_T * SCAN_E)   // 4096 elems per scan block

__device__ __align__(16) float g_G[MAX_NODES * GP];
__device__ __align__(16) float g_bond[MAX_NODES * BP];
__device__ int g_hist[MAX_NODES];
__device__ int g_start[MAX_NODES + 1];
__device__ int g_cursor[MAX_NODES];
__device__ int g_bsum[64];
__device__ int g_bsumx[64];
__device__ int g_sorted_dst[MAX_EDGES];
__device__ int g_sorted_eid[MAX_EDGES];

// ---------------------------------------------------------------------------
// K0: zero histogram
// ---------------------------------------------------------------------------
__global__ void hist_zero_kernel(int n_nodes) {
    int i = blockIdx.x * blockDim.x + threadIdx.x;
    if (i < n_nodes) g_hist[i] = 0;
}

// ---------------------------------------------------------------------------
// K1: histogram of src
// ---------------------------------------------------------------------------
__global__ void hist_kernel(const int* __restrict__ src, int n_edges) {
    int e = blockIdx.x * blockDim.x + threadIdx.x;
    if (e < n_edges) atomicAdd(&g_hist[src[e]], 1);
}

// ---------------------------------------------------------------------------
// K2a: per-block exclusive scan (4096 elems/block), block totals to g_bsum
// ---------------------------------------------------------------------------
__global__ __launch_bounds__(SCAN_T) void scan1_kernel(int n) {
    __shared__ int wsum[32];
    int t = threadIdx.x;
    int base = blockIdx.x * SCAN_B + t * SCAN_E;

    int v[SCAN_E];
    int local = 0;
    #pragma unroll
    for (int j = 0; j < SCAN_E; j++) {
        v[j] = (base + j < n) ? g_hist[base + j] : 0;
        local += v[j];
    }
    int lane = t & 31, w = t >> 5;
    int inc = local;
    #pragma unroll
    for (int d = 1; d < 32; d <<= 1) {
        int x = __shfl_up_sync(0xFFFFFFFF, inc, d);
        if (lane >= d) inc += x;
    }
    if (lane == 31) wsum[w] = inc;
    __syncthreads();
    if (t < 32) {
        int x = wsum[t];
        #pragma unroll
        for (int d = 1; d < 32; d <<= 1) {
            int y = __shfl_up_sync(0xFFFFFFFF, x, d);
            if (t >= d) x += y;
        }
        wsum[t] = x;
    }
    __syncthreads();
    int excl = inc - local + ((w > 0) ? wsum[w - 1] : 0);
    int run = excl;
    #pragma unroll
    for (int j = 0; j < SCAN_E; j++) {
        if (base + j < n) g_start[base + j] = run;
        run += v[j];
    }
    if (t == SCAN_T - 1) g_bsum[blockIdx.x] = run;
}

// ---------------------------------------------------------------------------
// K2b: scan of block sums (single warp; nblocks <= 32 for 100K nodes)
// ---------------------------------------------------------------------------
__global__ void scan2_kernel(int nb) {
    int t = threadIdx.x;
    int x = (t < nb) ? g_bsum[t] : 0;
    int inc = x;
    #pragma unroll
    for (int d = 1; d < 32; d <<= 1) {
        int y = __shfl_up_sync(0xFFFFFFFF, inc, d);
        if (t >= d) inc += y;
    }
    if (t < nb) g_bsumx[t] = inc - x;
}

// ---------------------------------------------------------------------------
// K2c: add block offsets; init scatter cursors; cap entry
// ---------------------------------------------------------------------------
__global__ void scan3_kernel(int n, int n_edges) {
    int i = blockIdx.x * blockDim.x + threadIdx.x;
    if (i < n) {
        int v = g_start[i] + g_bsumx[i / SCAN_B];
        g_start[i] = v;
        g_cursor[i] = v;
    }
    if (i == 0) g_start[n] = n_edges;
}

// ---------------------------------------------------------------------------
// K3: scatter edges into per-src contiguous lists
// ---------------------------------------------------------------------------
__global__ void scatter_kernel(const int* __restrict__ src,
                               const int* __restrict__ dst,
                               int n_edges) {
    int e = blockIdx.x * blockDim.x + threadIdx.x;
    if (e >= n_edges) return;
    int s = src[e];
    int pos = atomicAdd(&g_cursor[s], 1);
    g_sorted_dst[pos] = dst[e];
    g_sorted_eid[pos] = e;
}

// ---------------------------------------------------------------------------
// K4: warp-per-node aggregation (no atomics).
//   lane l accumulates G[k] for k = l, l+32, l+64(<81); bond[l] for l<22.
//   Edge scale s_e derived from the gathered fd[0..2] via shfl.
// ---------------------------------------------------------------------------
__global__ __launch_bounds__(256) void agg_kernel(
    const float* __restrict__ feat,
    const float* __restrict__ bond,
    int n_nodes) {

    int warp = (blockIdx.x * 256 + threadIdx.x) >> 5;
    int lane = threadIdx.x & 31;
    if (warp >= n_nodes) return;
    int n = warp;

    int beg = __ldg(g_start + n);
    int end = __ldg(g_start + n + 1);

    // node's own coords (warp-uniform broadcast loads)
    const float* fs = feat + (size_t)n * NF;
    float fs0 = __ldg(fs + 0), fs1 = __ldg(fs + 1), fs2 = __ldg(fs + 2);

    float a0 = 0.f, a1 = 0.f, a2 = 0.f;   // G[lane], G[lane+32], G[lane+64]
    float ab = 0.f;                        // bond[lane]
    float ac = 0.f;                        // coeff (uniform across lanes)
    bool has2 = (lane < NF - 64);          // lane < 17
    bool hasb = (lane < NB);

    #pragma unroll 2
    for (int i = beg; i < end; i++) {
        int d = __ldg(g_sorted_dst + i);
        int e = __ldg(g_sorted_eid + i);
        const float* fd = feat + (size_t)d * NF;
        float v0 = __ldg(fd + lane);
        float v1 = __ldg(fd + lane + 32);
        float v2 = has2 ? __ldg(fd + lane + 64) : 0.f;
        float bv = hasb ? __ldg(bond + (size_t)e * NB + lane) : 0.f;

        float fd0 = __shfl_sync(0xFFFFFFFF, v0, 0);
        float fd1 = __shfl_sync(0xFFFFFFFF, v0, 1);
        float fd2 = __shfl_sync(0xFFFFFFFF, v0, 2);
        float dx = fs0 - fd0, dy = fs1 - fd1, dz = fs2 - fd2;
        float dd = dx * dx + dy * dy + dz * dz;
        float s = (dd > 0.f) ? (1.f / dd) : 10000.f;

        a0 += s * v0;
        a1 += s * v1;
        a2 += s * v2;
        ab += bv;
        ac += s;
    }

    float* Gr = g_G + (size_t)n * GP;
    Gr[lane] = a0;
    Gr[lane + 32] = a1;
    if (has2) Gr[lane + 64] = a2;
    if (lane == 18) Gr[NF] = ac;     // coeff packed at G[81]
    if (hasb) g_bond[(size_t)n * BP + lane] = ab;
}

// ---------------------------------------------------------------------------
// K5: final GEMM. One node per thread; 64 channels as 32 packed f32x2 accs;
// W broadcast from smem via LDS.128; fma.rn.f32x2.
// ---------------------------------------------------------------------------
__device__ __forceinline__ void fma2_step(unsigned long long* acc,
                                          const float* wrow, float xv) {
    unsigned long long xx;
    asm("mov.b64 %0, {%1, %1};" : "=l"(xx) : "f"(xv));
    const ulonglong2* w2 = reinterpret_cast<const ulonglong2*>(wrow);
    #pragma unroll
    for (int j = 0; j < 16; j++) {
        ulonglong2 wv = w2[j];
        asm("fma.rn.f32x2 %0, %1, %2, %0;" : "+l"(acc[2 * j + 0]) : "l"(xx), "l"(wv.x));
        asm("fma.rn.f32x2 %0, %1, %2, %0;" : "+l"(acc[2 * j + 1]) : "l"(xx), "l"(wv.y));
    }
}

__global__ __launch_bounds__(256) void final_kernel(
    const float* __restrict__ feat,
    const float* __restrict__ w_s,   // [81][64]
    const float* __restrict__ w_n,   // [103][64]
    float* __restrict__ out,         // [n_nodes][64]
    int n_nodes) {

    __shared__ __align__(16) float Wsh[184 * OC];   // 47104 B

    int tid = threadIdx.x;
    int node = blockIdx.x * 256 + tid;

    #pragma unroll
    for (int r = 0; r < 46; r++) {                  // 46*256 == 184*64
        int idx = r * 256 + tid;
        int k = idx >> 6;
        int c = idx & (OC - 1);
        Wsh[idx] = (k < NF) ? __ldg(w_s + k * OC + c)
                            : __ldg(w_n + (k - NF) * OC + c);
    }
    __syncthreads();

    if (node >= n_nodes) return;

    const float* frow = feat + (size_t)node * NF;
    const float* Grow = g_G + (size_t)node * GP;
    const float* brow = g_bond + (size_t)node * BP;
    float cn = __ldg(Grow + NF);

    unsigned long long acc[32];
    #pragma unroll
    for (int j = 0; j < 32; j++) acc[j] = 0ull;

    // segment 1: feat (rows 0..80)
    #pragma unroll 3
    for (int k = 0; k < NF; k++)
        fma2_step(acc, Wsh + k * OC, __ldg(frow + k));
    // segment 2: G (+ cn*feat for k>=3), rows 81..161
    fma2_step(acc, Wsh + (NF + 0) * OC, __ldg(Grow + 0));
    fma2_step(acc, Wsh + (NF + 1) * OC, __ldg(Grow + 1));
    fma2_step(acc, Wsh + (NF + 2) * OC, __ldg(Grow + 2));
    #pragma unroll 3
    for (int k = 3; k < NF; k++)
        fma2_step(acc, Wsh + (NF + k) * OC, __ldg(Grow + k) + cn * __ldg(frow + k));
    // segment 3: bond_agg, rows 162..183
    #pragma unroll 2
    for (int k = 0; k < NB; k++)
        fma2_step(acc, Wsh + (2 * NF + k) * OC, __ldg(brow + k));

    float* orow = out + (size_t)node * OC;
    #pragma unroll
    for (int j = 0; j < 16; j++) {
        float x0, x1, x2, x3;
        asm("mov.b64 {%0, %1}, %2;" : "=f"(x0), "=f"(x1) : "l"(acc[2 * j + 0]));
        asm("mov.b64 {%0, %1}, %2;" : "=f"(x2), "=f"(x3) : "l"(acc[2 * j + 1]));
        reinterpret_cast<float4*>(orow)[j] = make_float4(x0, x1, x2, x3);
    }
}

// ---------------------------------------------------------------------------
// Launch
// ---------------------------------------------------------------------------
extern "C" void kernel_launch(void* const* d_in, const int* in_sizes, int n_in,
                              void* d_out, int out_size) {
    const float* feat = (const float*)d_in[0];
    const float* bond = (const float*)d_in[1];
    const float* w_s  = (const float*)d_in[2];
    const float* w_n  = (const float*)d_in[3];
    const int*   src  = (const int*)d_in[4];
    const int*   dst  = (const int*)d_in[5];
    float* out = (float*)d_out;

    int n_nodes = in_sizes[0] / NF;
    int n_edges = in_sizes[4];
    int nsb = (n_nodes + SCAN_B - 1) / SCAN_B;   // scan blocks (25 for 100K)

    hist_zero_kernel<<<(n_nodes + 255) / 256, 256>>>(n_nodes);
    hist_kernel<<<(n_edges + 255) / 256, 256>>>(src, n_edges);
    scan1_kernel<<<nsb, SCAN_T>>>(n_nodes);
    scan2_kernel<<<1, 32>>>(nsb);
    scan3_kernel<<<(n_nodes + 255) / 256, 256>>>(n_nodes, n_edges);
    scatter_kernel<<<(n_edges + 255) / 256, 256>>>(src, dst, n_edges);
    agg_kernel<<<(n_nodes * 32 + 255) / 256, 256>>>(feat, bond, n_nodes);
    final_kernel<<<(n_nodes + 255) / 256, 256>>>(feat, w_s, w_n, out, n_nodes);
}

// round 4
// speedup vs baseline: 1.5499x; 1.1462x over previous
#include <cuda_runtime.h>

// RuleGraphConvLayer — GB300 sm_103a, round 4
//
//   x[n] = [feat(81) | G + c*feat*(k>=3)(81) | bagg(22)]  (packed by agg)
//   out[n] = x[n] @ [w_s ; w_n]   (K=184, N=64)
//
// R4: agg emits a packed, 16B-aligned x-row so the final GEMM reads x with
// LDG.128 (4x fewer L1tex wavefronts than R3's scalar row-walk). agg loop is
// 2-edge software-pipelined; sorted (dst,eid) stored as int2.

#define MAX_NODES 100000
#define MAX_EDGES 800000
#define NF 81
#define NB 22
#define OC 64
#define KTOT 184
#define XP 188     // x row pitch: 188*4 = 752 B = 47*16 -> every row 16B aligned

#define SCAN_T 1024
#define SCAN_E 4
#define SCAN_B (SCAN_T * SCAN_E)

__device__ __align__(16) float g_x[MAX_NODES * XP];
__device__ int g_hist[MAX_NODES];
__device__ int g_start[MAX_NODES + 1];
__device__ int g_cursor[MAX_NODES];
__device__ int g_bsum[64];
__device__ int g_bsumx[64];
__device__ __align__(8) int2 g_sorted[MAX_EDGES];

// ---------------------------------------------------------------------------
__global__ void hist_zero_kernel(int n_nodes) {
    int i = blockIdx.x * blockDim.x + threadIdx.x;
    if (i < n_nodes) g_hist[i] = 0;
}

__global__ void hist_kernel(const int* __restrict__ src, int n_edges) {
    int e = blockIdx.x * blockDim.x + threadIdx.x;
    if (e < n_edges) atomicAdd(&g_hist[src[e]], 1);
}

// per-block exclusive scan, totals to g_bsum
__global__ __launch_bounds__(SCAN_T) void scan1_kernel(int n) {
    __shared__ int wsum[32];
    int t = threadIdx.x;
    int base = blockIdx.x * SCAN_B + t * SCAN_E;
    int v[SCAN_E];
    int local = 0;
    #pragma unroll
    for (int j = 0; j < SCAN_E; j++) {
        v[j] = (base + j < n) ? g_hist[base + j] : 0;
        local += v[j];
    }
    int lane = t & 31, w = t >> 5;
    int inc = local;
    #pragma unroll
    for (int d = 1; d < 32; d <<= 1) {
        int x = __shfl_up_sync(0xFFFFFFFF, inc, d);
        if (lane >= d) inc += x;
    }
    if (lane == 31) wsum[w] = inc;
    __syncthreads();
    if (t < 32) {
        int x = wsum[t];
        #pragma unroll
        for (int d = 1; d < 32; d <<= 1) {
            int y = __shfl_up_sync(0xFFFFFFFF, x, d);
            if (t >= d) x += y;
        }
        wsum[t] = x;
    }
    __syncthreads();
    int run = inc - local + ((w > 0) ? wsum[w - 1] : 0);
    #pragma unroll
    for (int j = 0; j < SCAN_E; j++) {
        if (base + j < n) g_start[base + j] = run;
        run += v[j];
    }
    if (t == SCAN_T - 1) g_bsum[blockIdx.x] = run;
}

__global__ void scan2_kernel(int nb) {
    int t = threadIdx.x;
    int x = (t < nb) ? g_bsum[t] : 0;
    int inc = x;
    #pragma unroll
    for (int d = 1; d < 32; d <<= 1) {
        int y = __shfl_up_sync(0xFFFFFFFF, inc, d);
        if (t >= d) inc += y;
    }
    if (t < nb) g_bsumx[t] = inc - x;
}

__global__ void scan3_kernel(int n, int n_edges) {
    int i = blockIdx.x * blockDim.x + threadIdx.x;
    if (i < n) {
        int v = g_start[i] + g_bsumx[i / SCAN_B];
        g_start[i] = v;
        g_cursor[i] = v;
    }
    if (i == 0) g_start[n] = n_edges;
}

__global__ void scatter_kernel(const int* __restrict__ src,
                               const int* __restrict__ dst,
                               int n_edges) {
    int e = blockIdx.x * blockDim.x + threadIdx.x;
    if (e >= n_edges) return;
    int s = src[e];
    int pos = atomicAdd(&g_cursor[s], 1);
    g_sorted[pos] = make_int2(dst[e], e);
}

// ---------------------------------------------------------------------------
// agg: warp per node. Gathers feat[dst]/bond, reduces in registers, writes the
// fully-packed x row. 2-edge software pipeline (8 gathers in flight).
// ---------------------------------------------------------------------------
__global__ __launch_bounds__(256) void agg_kernel(
    const float* __restrict__ feat,
    const float* __restrict__ bond,
    int n_nodes) {

    int n = (int)((blockIdx.x * 256 + threadIdx.x) >> 5);
    int lane = threadIdx.x & 31;
    if (n >= n_nodes) return;

    int beg = __ldg(g_start + n);
    int end = __ldg(g_start + n + 1);

    // own feature row (coalesced, lane-indexed)
    const float* fs = feat + (size_t)n * NF;
    bool has2 = (lane < NF - 64);   // lane < 17
    bool hasb = (lane < NB);
    float f0 = __ldg(fs + lane);
    float f1 = __ldg(fs + lane + 32);
    float f2 = has2 ? __ldg(fs + lane + 64) : 0.f;
    float fs0 = __shfl_sync(0xFFFFFFFF, f0, 0);
    float fs1 = __shfl_sync(0xFFFFFFFF, f0, 1);
    float fs2 = __shfl_sync(0xFFFFFFFF, f0, 2);

    float a0 = 0.f, a1 = 0.f, a2 = 0.f, ab = 0.f, ac = 0.f;

    int i = beg;
    for (; i + 1 < end; i += 2) {
        int2 p0 = __ldg(g_sorted + i);
        int2 p1 = __ldg(g_sorted + i + 1);
        const float* fdA = feat + (size_t)p0.x * NF;
        const float* fdB = feat + (size_t)p1.x * NF;
        float u0 = __ldg(fdA + lane);
        float w0 = __ldg(fdB + lane);
        float u1 = __ldg(fdA + lane + 32);
        float w1 = __ldg(fdB + lane + 32);
        float u2 = has2 ? __ldg(fdA + lane + 64) : 0.f;
        float w2 = has2 ? __ldg(fdB + lane + 64) : 0.f;
        float bu = hasb ? __ldg(bond + (size_t)p0.y * NB + lane) : 0.f;
        float bw = hasb ? __ldg(bond + (size_t)p1.y * NB + lane) : 0.f;

        float dxA = fs0 - __shfl_sync(0xFFFFFFFF, u0, 0);
        float dyA = fs1 - __shfl_sync(0xFFFFFFFF, u0, 1);
        float dzA = fs2 - __shfl_sync(0xFFFFFFFF, u0, 2);
        float ddA = dxA * dxA + dyA * dyA + dzA * dzA;
        float sA = (ddA > 0.f) ? (1.f / ddA) : 10000.f;

        float dxB = fs0 - __shfl_sync(0xFFFFFFFF, w0, 0);
        float dyB = fs1 - __shfl_sync(0xFFFFFFFF, w0, 1);
        float dzB = fs2 - __shfl_sync(0xFFFFFFFF, w0, 2);
        float ddB = dxB * dxB + dyB * dyB + dzB * dzB;
        float sB = (ddB > 0.f) ? (1.f / ddB) : 10000.f;

        a0 += sA * u0 + sB * w0;
        a1 += sA * u1 + sB * w1;
        a2 += sA * u2 + sB * w2;
        ab += bu + bw;
        ac += sA + sB;
    }
    if (i < end) {
        int2 p0 = __ldg(g_sorted + i);
        const float* fdA = feat + (size_t)p0.x * NF;
        float u0 = __ldg(fdA + lane);
        float u1 = __ldg(fdA + lane + 32);
        float u2 = has2 ? __ldg(fdA + lane + 64) : 0.f;
        float bu = hasb ? __ldg(bond + (size_t)p0.y * NB + lane) : 0.f;
        float dxA = fs0 - __shfl_sync(0xFFFFFFFF, u0, 0);
        float dyA = fs1 - __shfl_sync(0xFFFFFFFF, u0, 1);
        float dzA = fs2 - __shfl_sync(0xFFFFFFFF, u0, 2);
        float ddA = dxA * dxA + dyA * dyA + dzA * dzA;
        float sA = (ddA > 0.f) ? (1.f / ddA) : 10000.f;
        a0 += sA * u0;
        a1 += sA * u1;
        a2 += sA * u2;
        ab += bu;
        ac += sA;
    }

    // write packed x row (coalesced lane stores)
    float* xr = g_x + (size_t)n * XP;
    xr[lane] = f0;
    xr[lane + 32] = f1;
    if (has2) xr[lane + 64] = f2;
    xr[NF + lane]      = (lane >= 3) ? (a0 + ac * f0) : a0;   // k = lane
    xr[NF + lane + 32] = a1 + ac * f1;                        // k >= 32
    if (has2) xr[NF + lane + 64] = a2 + ac * f2;
    if (hasb) xr[2 * NF + lane] = ab;
}

// ---------------------------------------------------------------------------
// final GEMM: one node per thread, 64 ch as 32 packed f32x2 accumulators.
// x via LDG.128 (46 vec loads), W broadcast from smem via LDS.128, FFMA2.
// ---------------------------------------------------------------------------
__device__ __forceinline__ void fma2_step(unsigned long long* acc,
                                          const float* wrow, float xv) {
    unsigned long long xx;
    asm("mov.b64 %0, {%1, %1};" : "=l"(xx) : "f"(xv));
    const ulonglong2* w2 = reinterpret_cast<const ulonglong2*>(wrow);
    #pragma unroll
    for (int j = 0; j < 16; j++) {
        ulonglong2 wv = w2[j];
        asm("fma.rn.f32x2 %0, %1, %2, %0;" : "+l"(acc[2 * j + 0]) : "l"(xx), "l"(wv.x));
        asm("fma.rn.f32x2 %0, %1, %2, %0;" : "+l"(acc[2 * j + 1]) : "l"(xx), "l"(wv.y));
    }
}

__global__ __launch_bounds__(256) void final_kernel(
    const float* __restrict__ w_s,   // [81][64]
    const float* __restrict__ w_n,   // [103][64]
    float* __restrict__ out,         // [n_nodes][64]
    int n_nodes) {

    __shared__ __align__(16) float Wsh[KTOT * OC];   // 47104 B

    int tid = threadIdx.x;
    int node = blockIdx.x * 256 + tid;

    #pragma unroll
    for (int r = 0; r < 46; r++) {                   // 46*256 == 184*64
        int idx = r * 256 + tid;
        int k = idx >> 6;
        int c = idx & (OC - 1);
        Wsh[idx] = (k < NF) ? __ldg(w_s + k * OC + c)
                            : __ldg(w_n + (k - NF) * OC + c);
    }
    __syncthreads();

    if (node >= n_nodes) return;

    const float4* xrow = reinterpret_cast<const float4*>(g_x + (size_t)node * XP);

    unsigned long long acc[32];
    #pragma unroll
    for (int j = 0; j < 32; j++) acc[j] = 0ull;

    float4 xv = __ldg(xrow);               // prefetch
    const float* wp = Wsh;
    #pragma unroll 2
    for (int k4 = 0; k4 < 46; k4++) {
        float4 cur = xv;
        if (k4 + 1 < 46) xv = __ldg(xrow + k4 + 1);
        fma2_step(acc, wp,          cur.x);
        fma2_step(acc, wp + OC,     cur.y);
        fma2_step(acc, wp + 2 * OC, cur.z);
        fma2_step(acc, wp + 3 * OC, cur.w);
        wp += 4 * OC;
    }

    float* orow = out + (size_t)node * OC;
    #pragma unroll
    for (int j = 0; j < 16; j++) {
        float x0, x1, x2, x3;
        asm("mov.b64 {%0, %1}, %2;" : "=f"(x0), "=f"(x1) : "l"(acc[2 * j + 0]));
        asm("mov.b64 {%0, %1}, %2;" : "=f"(x2), "=f"(x3) : "l"(acc[2 * j + 1]));
        reinterpret_cast<float4*>(orow)[j] = make_float4(x0, x1, x2, x3);
    }
}

// ---------------------------------------------------------------------------
extern "C" void kernel_launch(void* const* d_in, const int* in_sizes, int n_in,
                              void* d_out, int out_size) {
    const float* feat = (const float*)d_in[0];
    const float* bond = (const float*)d_in[1];
    const float* w_s  = (const float*)d_in[2];
    const float* w_n  = (const float*)d_in[3];
    const int*   src  = (const int*)d_in[4];
    const int*   dst  = (const int*)d_in[5];
    float* out = (float*)d_out;

    int n_nodes = in_sizes[0] / NF;
    int n_edges = in_sizes[4];
    int nsb = (n_nodes + SCAN_B - 1) / SCAN_B;

    hist_zero_kernel<<<(n_nodes + 255) / 256, 256>>>(n_nodes);
    hist_kernel<<<(n_edges + 255) / 256, 256>>>(src, n_edges);
    scan1_kernel<<<nsb, SCAN_T>>>(n_nodes);
    scan2_kernel<<<1, 32>>>(nsb);
    scan3_kernel<<<(n_nodes + 255) / 256, 256>>>(n_nodes, n_edges);
    scatter_kernel<<<(n_edges + 255) / 256, 256>>>(src, dst, n_edges);
    agg_kernel<<<(n_nodes * 32 + 255) / 256, 256>>>(feat, bond, n_nodes);
    final_kernel<<<(n_nodes + 255) / 256, 256>>>(w_s, w_n, out, n_nodes);
}